// round 17
// baseline (speedup 1.0000x reference)
#include <cuda_runtime.h>
#include <cuda_bf16.h>
#include <cstdint>
#include <cstddef>

#define LSEQ   2048
#define DMODEL 1024
#define NSTATE 32
#define VOCAB  32000

// tcgen05 is arch-specific (sm_103a). The harness build includes a compute_103
// (non-'a') PTX pass where tcgen05.* is illegal — gate on the feature macro.
#if defined(__CUDA_ARCH_FEAT_SM103_ALL) || defined(__CUDA_ARCH_FEAT_SM100_ALL)
#define HAS_TCGEN05 1
#else
#define HAS_TCGEN05 0
#endif

// ---------------- scratch (static __device__, no allocations) ----------------
__device__ float g_xin[LSEQ*DMODEL];        // row-major (gated_bc)
__device__ float g_xin_t[DMODEL*LSEQ];
__device__ float g_z_t[DMODEL*LSEQ];
__device__ float g_delta_t[DMODEL*LSEQ];
__device__ float g_Bseq[NSTATE*LSEQ];
__device__ float g_Cseq[NSTATE*LSEQ];
__device__ float g_ut[DMODEL*LSEQ];
__device__ float g_u[LSEQ*DMODEL];
// bf16 hi/lo split operand pairs
__device__ __nv_bfloat16 g_x_hi[LSEQ*DMODEL],   g_x_lo[LSEQ*DMODEL];
__device__ __nv_bfloat16 g_win_hi[2*DMODEL*DMODEL], g_win_lo[2*DMODEL*DMODEL];
__device__ __nv_bfloat16 g_wd_hi[DMODEL*DMODEL],    g_wd_lo[DMODEL*DMODEL];
__device__ __nv_bfloat16 g_wo_hi[DMODEL*DMODEL],    g_wo_lo[DMODEL*DMODEL];
__device__ __nv_bfloat16 g_xin_hi[LSEQ*DMODEL], g_xin_lo[LSEQ*DMODEL];
__device__ __nv_bfloat16 g_ln_hi[LSEQ*DMODEL],  g_ln_lo[LSEQ*DMODEL];
__device__ __nv_bfloat16 g_mid_hi[LSEQ*DMODEL], g_mid_lo[LSEQ*DMODEL];
__device__ __nv_bfloat16 g_wv_hi[(size_t)VOCAB*DMODEL], g_wv_lo[(size_t)VOCAB*DMODEL];

// ======================= PTX helpers ==========================================
__device__ __forceinline__ uint32_t smem_u32(const void* p) {
    uint32_t a;
    asm("{ .reg .u64 t; cvta.to.shared.u64 t, %1; cvt.u32.u64 %0, t; }"
        : "=r"(a) : "l"(p));
    return a;
}
__device__ __forceinline__ uint32_t elect_one() {
    uint32_t pred;
    asm volatile("{\n\t.reg .pred p;\n\telect.sync _|p, 0xFFFFFFFF;\n\t"
                 "selp.b32 %0, 1, 0, p;\n\t}" : "=r"(pred));
    return pred;
}
#define MBARRIER_INIT(addr, cnt) \
    asm volatile("mbarrier.init.shared.b64 [%0], %1;" :: "r"(addr), "r"(cnt) : "memory")
#define MBARRIER_INVAL(addr) \
    asm volatile("mbarrier.inval.shared.b64 [%0];" :: "r"(addr) : "memory")
#define MBARRIER_WAIT_PARITY(addr, par) do {                                   \
    uint32_t _m = (addr), _p = (par), _d;                                      \
    asm volatile("{\n\t.reg .pred p;\n\t"                                      \
        "mbarrier.try_wait.parity.acquire.cta.shared::cta.b64 p, [%1], %2;\n\t"\
        "selp.b32 %0, 1, 0, p;\n\t}" : "=r"(_d) : "r"(_m), "r"(_p) : "memory");\
    if (!_d) {                                                                 \
        asm volatile("{\n\t.reg .pred P1;\n\tWL_%=:\n\t"                       \
            "mbarrier.try_wait.parity.acquire.cta.shared::cta.b64 P1, [%0], %1, 0x989680;\n\t" \
            "@P1 bra.uni WD_%=;\n\tbra.uni WL_%=;\n\tWD_%=:\n\t}"              \
            :: "r"(_m), "r"(_p) : "memory");                                   \
    }                                                                          \
} while (0)
#define FENCE_PROXY_ASYNC() asm volatile("fence.proxy.async.shared::cta;" ::: "memory")
// cp.async (sm_80 baseline: legal on compute_103 AND sm_103a)
__device__ __forceinline__ void cp_async16(uint32_t dst, const void* src) {
    asm volatile("cp.async.cg.shared.global [%0], [%1], 16;"
                 :: "r"(dst), "l"(src) : "memory");
}
#define CP_COMMIT() asm volatile("cp.async.commit_group;" ::: "memory")
#define CP_WAIT0()  asm volatile("cp.async.wait_group 0;" ::: "memory")

#if HAS_TCGEN05
#define TCGEN05_ALLOC(sm_addr, ncols) \
    asm volatile("tcgen05.alloc.cta_group::1.sync.aligned.shared::cta.b32 [%0], %1;" \
                 :: "r"(sm_addr), "r"(ncols) : "memory")
#define TCGEN05_DEALLOC(tm, ncols) \
    asm volatile("tcgen05.dealloc.cta_group::1.sync.aligned.b32 %0, %1;" :: "r"(tm), "r"(ncols))
#define TCGEN05_RELINQ() \
    asm volatile("tcgen05.relinquish_alloc_permit.cta_group::1.sync.aligned;")
#define TCGEN05_COMMIT(mbar) \
    asm volatile("tcgen05.commit.cta_group::1.mbarrier::arrive::one.shared::cluster.b64 [%0];" \
                 :: "r"(mbar) : "memory")
#define TCGEN05_WAIT_LD()  asm volatile("tcgen05.wait::ld.sync.aligned;" ::: "memory")
#define TCGEN05_FENCE_AFTER()  asm volatile("tcgen05.fence::after_thread_sync;" ::: "memory")
#define TCGEN05_FENCE_BEFORE() asm volatile("tcgen05.fence::before_thread_sync;" ::: "memory")
#define TCGEN05_LD_X32(r, addr) \
    asm volatile("tcgen05.ld.sync.aligned.32x32b.x32.b32 " \
        "{%0,%1,%2,%3,%4,%5,%6,%7,%8,%9,%10,%11,%12,%13,%14,%15," \
        "%16,%17,%18,%19,%20,%21,%22,%23,%24,%25,%26,%27,%28,%29,%30,%31}, [%32];" \
        : "=r"((r)[0]),"=r"((r)[1]),"=r"((r)[2]),"=r"((r)[3]), \
          "=r"((r)[4]),"=r"((r)[5]),"=r"((r)[6]),"=r"((r)[7]), \
          "=r"((r)[8]),"=r"((r)[9]),"=r"((r)[10]),"=r"((r)[11]), \
          "=r"((r)[12]),"=r"((r)[13]),"=r"((r)[14]),"=r"((r)[15]), \
          "=r"((r)[16]),"=r"((r)[17]),"=r"((r)[18]),"=r"((r)[19]), \
          "=r"((r)[20]),"=r"((r)[21]),"=r"((r)[22]),"=r"((r)[23]), \
          "=r"((r)[24]),"=r"((r)[25]),"=r"((r)[26]),"=r"((r)[27]), \
          "=r"((r)[28]),"=r"((r)[29]),"=r"((r)[30]),"=r"((r)[31]) \
        : "r"(addr))
#endif  // HAS_TCGEN05

// SW128 K-major smem descriptor: layout=SW128, version=1(Blackwell), SBO=64, LBO=1
static constexpr unsigned long long SMEM_DESC_BASE_SW128 =
    (2ull << 61) | (1ull << 46) | (64ull << 32) | (1ull << 16);
#define MAKE_SMEM_DESC(a) (SMEM_DESC_BASE_SW128 | ((unsigned long long)((a) >> 4) & 0x3FFF))
#define SWZ128(off) ((off) ^ (((off) >> 3) & 0x70))

#if HAS_TCGEN05
__device__ __forceinline__ void mma_f16_ss(uint32_t d, unsigned long long ad,
                                           unsigned long long bd, uint32_t idesc,
                                           uint32_t en) {
    asm volatile(
        "{\n\t.reg .pred p;\n\tsetp.ne.u32 p, %5, 0;\n\t"
        "tcgen05.mma.cta_group::1.kind::f16 [%0], %1, %2, %3, {%4,%4,%4,%4}, p;\n\t}"
        :: "r"(d), "l"(ad), "l"(bd), "r"(idesc), "r"(0u), "r"(en) : "memory");
}
#endif

// ================= fp32 -> bf16 hi/lo split ==================================
__device__ __forceinline__ void split_store(__nv_bfloat16* hi, __nv_bfloat16* lo,
                                            int i, float4 v)
{
    float vv[4] = {v.x, v.y, v.z, v.w};
    __nv_bfloat16 h4[4], l4[4];
#pragma unroll
    for (int j = 0; j < 4; j++) {
        __nv_bfloat16 h = __float2bfloat16(vv[j]);
        h4[j] = h;
        l4[j] = __float2bfloat16(vv[j] - __bfloat162float(h));
    }
    *(uint2*)(hi + (size_t)i * 4) = *(uint2*)h4;
    *(uint2*)(lo + (size_t)i * 4) = *(uint2*)l4;
}

// 3-segment split: x, W_in, W_delta (everything WIN/DELTA need)
#define N4_X   (LSEQ * DMODEL / 4)
#define N4_WIN (2 * DMODEL * DMODEL / 4)
#define N4_WD  (DMODEL * DMODEL / 4)
#define N4_S3  (N4_X + N4_WIN + N4_WD)

__global__ __launch_bounds__(256) void split3_kernel(
    const float* __restrict__ sx, const float* __restrict__ swin,
    const float* __restrict__ swd)
{
    const int stride = gridDim.x * 256;
    const int i0 = blockIdx.x * 256 + threadIdx.x;
    float4 v[4];
    int    idx[4];
    bool   ok[4];
#pragma unroll
    for (int k = 0; k < 4; k++) {
        int i = i0 + k * stride;
        idx[k] = i;
        ok[k] = (i < N4_S3);
        if (ok[k]) {
            const float4* src;
            int j;
            if (i < N4_X)              { src = (const float4*)sx;   j = i; }
            else if (i < N4_X + N4_WIN){ src = (const float4*)swin; j = i - N4_X; }
            else                       { src = (const float4*)swd;  j = i - N4_X - N4_WIN; }
            v[k] = src[j];
        }
    }
#pragma unroll
    for (int k = 0; k < 4; k++) {
        if (!ok[k]) continue;
        int i = idx[k];
        if (i < N4_X)               split_store(g_x_hi,   g_x_lo,   i, v[k]);
        else if (i < N4_X + N4_WIN) split_store(g_win_hi, g_win_lo, i - N4_X, v[k]);
        else                        split_store(g_wd_hi,  g_wd_lo,  i - N4_X - N4_WIN, v[k]);
    }
}

// single-tensor split (W_out / W_vocab), MLP=4
enum { SEL_WO = 0, SEL_WV = 1 };
__global__ __launch_bounds__(256) void split1_kernel(
    const float* __restrict__ src4f, int dst_sel, int n4)
{
    const float4* src = (const float4*)src4f;
    __nv_bfloat16* hi = dst_sel ? g_wv_hi : g_wo_hi;
    __nv_bfloat16* lo = dst_sel ? g_wv_lo : g_wo_lo;
    const int stride = gridDim.x * 256;
    const int i0 = blockIdx.x * 256 + threadIdx.x;
    float4 v[4];
    int    idx[4];
    bool   ok[4];
#pragma unroll
    for (int k = 0; k < 4; k++) {
        idx[k] = i0 + k * stride;
        ok[k] = (idx[k] < n4);
        if (ok[k]) v[k] = src[idx[k]];
    }
#pragma unroll
    for (int k = 0; k < 4; k++)
        if (ok[k]) split_store(hi, lo, idx[k], v[k]);
}

// ================= tcgen05 GEMM common =======================================
// K-chunk = 128 (8 chunks) to halve the measured ~5500cyc/chunk fixed overhead
// (sync + fence + mbarrier drain + issue round-trip). Single 192KB stage,
// serial per chunk. SW128 K-major blocked-atom layout: K=128 bf16 = 256B/row =
// TWO 128B atom-columns; atom-col 1 sits at rows*128B (A: +16KB=1024 units,
// B: +32KB=2048 units), per test_mma_iter.cu's validated descriptor offsets.
#define TCG_BM 128
#define TCG_BN 256
#define TCG_BK 128
#define TCG_NCHUNK (DMODEL / TCG_BK)            // 8
#define SM_TILE0 1024
#define STAGE_BYTES (192 * 1024)
#define VG_SMEM (SM_TILE0 + STAGE_BYTES)        // 197632 B
// idesc: F32 accum | BF16 a | BF16 b | N=256 | M=128 (K-major both)
#define VG_IDESC ((1u<<4) | (1u<<7) | (1u<<10) | ((TCG_BN/8)<<17) | ((TCG_BM/16)<<24))

#if HAS_TCGEN05
// Stage layout: A_hi [0,32K) (two 16K atom-col halves), A_lo [32K,64K),
//               B_hi [64K,128K) (two 32K halves),       B_lo [128K,192K)
__device__ __forceinline__ void tc_load_chunk_async(
    uint32_t base,
    const uint4* __restrict__ Ah, const uint4* __restrict__ Al,
    const uint4* __restrict__ Bh, const uint4* __restrict__ Bl,
    int c, int m0, int n0, int tid)
{
    // rows are 1024 bf16 = 128 x 16B granules; chunk c covers granules c*16..+15
#pragma unroll
    for (int t = tid; t < TCG_BM * 16; t += 256) {
        int row = t >> 4, g = t & 15;
        uint32_t sw = ((g >> 3) ? 16384u : 0u) +
                      SWZ128((uint32_t)(row * 128 + (g & 7) * 16));
        size_t gi = (size_t)(m0 + row) * 128 + c * 16 + g;
        cp_async16(base + sw,          Ah + gi);
        cp_async16(base + 32768 + sw,  Al + gi);
    }
#pragma unroll
    for (int t = tid; t < TCG_BN * 16; t += 256) {
        int row = t >> 4, g = t & 15;
        uint32_t sw = ((g >> 3) ? 32768u : 0u) +
                      SWZ128((uint32_t)(row * 128 + (g & 7) * 16));
        size_t gi = (size_t)(n0 + row) * 128 + c * 16 + g;
        cp_async16(base + 65536 + sw,  Bh + gi);
        cp_async16(base + 131072 + sw, Bl + gi);
    }
    CP_COMMIT();
}

// Mainloop: serial per-chunk (load -> MMA -> drain), 8 chunks.
// MMA accumulation order is identical to the K=64 version (64 k-steps of
// hh, hl, lh in the same sequence) -> bit-identical results.
__device__ __forceinline__ uint32_t tc_mainloop(
    char* smem, uint32_t sb,
    const uint4* Ah, const uint4* Al, const uint4* Bh, const uint4* Bl,
    int m0, int n0, int tid, int wid)
{
    if (wid == 0) { TCGEN05_ALLOC(sb, 256); TCGEN05_RELINQ(); }
    if (tid == 0) { MBARRIER_INIT(sb + 8, 1); }
    __syncthreads();
    uint32_t tmem;
    asm volatile("ld.shared.b32 %0, [%1];" : "=r"(tmem) : "r"(sb));

    const uint32_t st0 = sb + SM_TILE0;
    unsigned long long ahd = MAKE_SMEM_DESC(st0);
    unsigned long long ald = MAKE_SMEM_DESC(st0 + 32768);
    unsigned long long bhd = MAKE_SMEM_DESC(st0 + 65536);
    unsigned long long bld = MAKE_SMEM_DESC(st0 + 131072);

    int ph = 0;
    for (int c = 0; c < TCG_NCHUNK; c++) {
        tc_load_chunk_async(st0, Ah, Al, Bh, Bl, c, m0, n0, tid);
        CP_WAIT0();
        FENCE_PROXY_ASYNC();
        __syncthreads();                  // stage complete & visible
        if (wid == 0 && elect_one()) {
#pragma unroll
            for (int k = 0; k < 8; k++) { // K=16 per step; atom-col switch at k=4
                unsigned long long offA = (unsigned long long)((k >> 2) * 1024 + (k & 3) * 2);
                unsigned long long offB = (unsigned long long)((k >> 2) * 2048 + (k & 3) * 2);
                uint32_t en0 = (c == 0 && k == 0) ? 0u : 1u;
                mma_f16_ss(tmem, ahd + offA, bhd + offB, VG_IDESC, en0);
                mma_f16_ss(tmem, ahd + offA, bld + offB, VG_IDESC, 1u);
                mma_f16_ss(tmem, ald + offA, bhd + offB, VG_IDESC, 1u);
            }
            TCGEN05_COMMIT(sb + 8);
        }
        MBARRIER_WAIT_PARITY(sb + 8, ph); // MMAs drained -> safe to overwrite
        ph ^= 1;
    }
    TCGEN05_FENCE_AFTER();
    return tmem;
}

__device__ __forceinline__ void tc_finish(uint32_t sb, uint32_t tmem, int tid, int wid) {
    TCGEN05_FENCE_BEFORE();
    __syncthreads();
    if (tid == 0) { MBARRIER_INVAL(sb + 8); }
    __syncthreads();
    if (wid == 0) TCGEN05_DEALLOC(tmem, 256);
}
#endif  // HAS_TCGEN05

// ================= small tcgen05 GEMMs with fused epilogues ==================
enum { EPI_WIN = 0, EPI_DELTA = 1, EPI_WOUT = 2 };

template <int EPI>
__global__ __launch_bounds__(256, 1) void gemm_small_tc(
    const float* __restrict__ bias, const float* __restrict__ bias2)
{
    const __nv_bfloat16 *Ahp, *Alp, *Bhp, *Blp;
    if (EPI == EPI_WIN)        { Ahp = g_x_hi;   Alp = g_x_lo;   Bhp = g_win_hi; Blp = g_win_lo; }
    else if (EPI == EPI_DELTA) { Ahp = g_xin_hi; Alp = g_xin_lo; Bhp = g_wd_hi;  Blp = g_wd_lo;  }
    else                       { Ahp = g_ln_hi;  Alp = g_ln_lo;  Bhp = g_wo_hi;  Blp = g_wo_lo;  }
#if HAS_TCGEN05
    extern __shared__ char smem[];
    const uint32_t sb = smem_u32(smem);
    const int tid = threadIdx.x;
    const int wid = tid >> 5;
    const int lid = tid & 31;
    const int m0 = blockIdx.x * TCG_BM;
    const int n0 = blockIdx.y * TCG_BN;

    uint32_t tmem = tc_mainloop(smem, sb, (const uint4*)Ahp, (const uint4*)Alp,
                                (const uint4*)Bhp, (const uint4*)Blp, m0, n0, tid, wid);

    const int row = m0 + (wid & 3) * 32 + lid;
    const int colg = (wid >> 2) * 128;
    const uint32_t woff = (uint32_t)(wid & 3) << 21;
#pragma unroll
    for (int cb = 0; cb < 4; cb++) {
        uint32_t d[32];
        TCGEN05_LD_X32(d, tmem + woff + colg + cb * 32);
        TCGEN05_WAIT_LD();
        const int c0 = n0 + colg + cb * 32;
        if (EPI == EPI_WIN) {
            if (c0 < DMODEL) {
#pragma unroll
                for (int j = 0; j < 32; j++) {
                    int cc = c0 + j;
                    float val = __uint_as_float(d[j]) + __ldg(bias + cc);
                    g_xin[(size_t)row * DMODEL + cc] = val;
                    g_xin_t[(size_t)cc * LSEQ + row] = val;
                    __nv_bfloat16 h = __float2bfloat16(val);
                    g_xin_hi[(size_t)row * DMODEL + cc] = h;
                    g_xin_lo[(size_t)row * DMODEL + cc] =
                        __float2bfloat16(val - __bfloat162float(h));
                }
            } else {
#pragma unroll
                for (int j = 0; j < 32; j++) {
                    int cc = c0 + j;
                    float val = __uint_as_float(d[j]) + __ldg(bias + cc);
                    g_z_t[(size_t)(cc - DMODEL) * LSEQ + row] = 1.f / (1.f + expf(-val));
                }
            }
        } else if (EPI == EPI_DELTA) {
#pragma unroll
            for (int j = 0; j < 32; j++) {
                int cc = c0 + j;
                float val = __uint_as_float(d[j]) + __ldg(bias + cc) + __ldg(bias2 + cc);
                g_delta_t[(size_t)cc * LSEQ + row] =
                    (val > 20.f) ? val : log1pf(expf(val));
            }
        } else {  // EPI_WOUT
#pragma unroll
            for (int j = 0; j < 32; j++) {
                int cc = c0 + j;
                float val = __uint_as_float(d[j]) + __ldg(bias + cc);
                __nv_bfloat16 h = __float2bfloat16(val);
                g_mid_hi[(size_t)row * DMODEL + cc] = h;
                g_mid_lo[(size_t)row * DMODEL + cc] =
                    __float2bfloat16(val - __bfloat162float(h));
            }
        }
    }
    tc_finish(sb, tmem, tid, wid);
#else
    // -------- fallback (compute_103 pass): fp32 tiled, hi+lo reconstruction --
    extern __shared__ char smem[];
    float* As = (float*)smem;            // [16][128]
    float* Bs = (float*)(smem + 8192);
    const int tid = threadIdx.x;
    const int tx = tid & 15;
    const int ty = tid >> 4;
    const int m0 = blockIdx.x * TCG_BM;
    const int n0b = blockIdx.y * TCG_BN;

    for (int h = 0; h < 2; h++) {
        const int n0 = n0b + h * 128;
        float acc[8][8];
#pragma unroll
        for (int i = 0; i < 8; i++)
#pragma unroll
            for (int j = 0; j < 8; j++) acc[i][j] = 0.f;
        for (int k0 = 0; k0 < DMODEL; k0 += 16) {
            for (int t = tid; t < 128 * 16; t += 256) {
                int r = t >> 4, c = t & 15;
                size_t ia = (size_t)(m0 + r) * DMODEL + k0 + c;
                As[c * 128 + r] = __bfloat162float(Ahp[ia]) + __bfloat162float(Alp[ia]);
                size_t ib = (size_t)(n0 + r) * DMODEL + k0 + c;
                Bs[c * 128 + r] = __bfloat162float(Bhp[ib]) + __bfloat162float(Blp[ib]);
            }
            __syncthreads();
#pragma unroll
            for (int kk = 0; kk < 16; kk++) {
                float a[8], b[8];
#pragma unroll
                for (int i = 0; i < 8; i++) a[i] = As[kk * 128 + ty * 8 + i];
#pragma unroll
                for (int j = 0; j < 8; j++) b[j] = Bs[kk * 128 + tx * 8 + j];
#pragma unroll
                for (int i = 0; i < 8; i++)
#pragma unroll
                    for (int j = 0; j < 8; j++) acc[i][j] += a[i] * b[j];
            }
            __syncthreads();
        }
#pragma unroll
        for (int i = 0; i < 8; i++) {
            int row = m0 + ty * 8 + i;
#pragma unroll
            for (int j = 0; j < 8; j++) {
                int cc = n0 + tx * 8 + j;
                float val = acc[i][j] + bias[cc];
                if (EPI == EPI_WIN) {
                    if (cc < DMODEL) {
                        g_xin[(size_t)row * DMODEL + cc] = val;
                        g_xin_t[(size_t)cc * LSEQ + row] = val;
                        __nv_bfloat16 hh = __float2bfloat16(val);
                        g_xin_hi[(size_t)row * DMODEL + cc] = hh;
                        g_xin_lo[(size_t)row * DMODEL + cc] =
                            __float2bfloat16(val - __bfloat162float(hh));
                    } else {
                        g_z_t[(size_t)(cc - DMODEL) * LSEQ + row] = 1.f / (1.f + expf(-val));
                    }
                } else if (EPI == EPI_DELTA) {
                    val += bias2[cc];
                    g_delta_t[(size_t)cc * LSEQ + row] =
                        (val > 20.f) ? val : log1pf(expf(val));
                } else {
                    __nv_bfloat16 hh = __float2bfloat16(val);
                    g_mid_hi[(size_t)row * DMODEL + cc] = hh;
                    g_mid_lo[(size_t)row * DMODEL + cc] =
                        __float2bfloat16(val - __bfloat162float(hh));
                }
            }
        }
    }
#endif
}

// ================= tcgen05 vocab GEMM ========================================
__global__ __launch_bounds__(256, 1) void vocab_gemm_tc(
    const float* __restrict__ bias, float* __restrict__ out)
{
#if HAS_TCGEN05
    extern __shared__ char smem[];
    const uint32_t sb = smem_u32(smem);
    const int tid = threadIdx.x;
    const int wid = tid >> 5;
    const int lid = tid & 31;
    const int m0 = blockIdx.x * TCG_BM;
    const int n0 = blockIdx.y * TCG_BN;

    uint32_t tmem = tc_mainloop(smem, sb,
                                (const uint4*)g_mid_hi, (const uint4*)g_mid_lo,
                                (const uint4*)g_wv_hi,  (const uint4*)g_wv_lo,
                                m0, n0, tid, wid);

    const int row = m0 + (wid & 3) * 32 + lid;
    const int colg = (wid >> 2) * 128;
    const uint32_t woff = (uint32_t)(wid & 3) << 21;
#pragma unroll
    for (int cb = 0; cb < 4; cb++) {
        uint32_t d[32];
        TCGEN05_LD_X32(d, tmem + woff + colg + cb * 32);
        TCGEN05_WAIT_LD();
        const int c0 = n0 + colg + cb * 32;
#pragma unroll
        for (int j = 0; j < 8; j++) {
            float4 r;
            r.x = __uint_as_float(d[4*j+0]) + __ldg(bias + c0 + 4*j + 0);
            r.y = __uint_as_float(d[4*j+1]) + __ldg(bias + c0 + 4*j + 1);
            r.z = __uint_as_float(d[4*j+2]) + __ldg(bias + c0 + 4*j + 2);
            r.w = __uint_as_float(d[4*j+3]) + __ldg(bias + c0 + 4*j + 3);
            *(float4*)(out + (size_t)row * VOCAB + c0 + 4*j) = r;
        }
    }
    tc_finish(sb, tmem, tid, wid);
#else
    extern __shared__ char smem[];
    float* As = (float*)smem;
    float* Bs = (float*)(smem + 8192);
    const int tid = threadIdx.x;
    const int tx = tid & 15;
    const int ty = tid >> 4;
    const int m0 = blockIdx.x * TCG_BM;
    const int n0b = blockIdx.y * TCG_BN;
    for (int h = 0; h < 2; h++) {
        const int n0 = n0b + h * 128;
        float acc[8][8];
#pragma unroll
        for (int i = 0; i < 8; i++)
#pragma unroll
            for (int j = 0; j < 8; j++) acc[i][j] = 0.f;
        for (int k0 = 0; k0 < DMODEL; k0 += 16) {
            for (int t = tid; t < 128 * 16; t += 256) {
                int r = t >> 4, c = t & 15;
                size_t ia = (size_t)(m0 + r) * DMODEL + k0 + c;
                As[c * 128 + r] = __bfloat162float(g_mid_hi[ia]) + __bfloat162float(g_mid_lo[ia]);
                size_t ib = (size_t)(n0 + r) * DMODEL + k0 + c;
                Bs[c * 128 + r] = __bfloat162float(g_wv_hi[ib]) + __bfloat162float(g_wv_lo[ib]);
            }
            __syncthreads();
#pragma unroll
            for (int kk = 0; kk < 16; kk++) {
                float a[8], b[8];
#pragma unroll
                for (int i = 0; i < 8; i++) a[i] = As[kk * 128 + ty * 8 + i];
#pragma unroll
                for (int j = 0; j < 8; j++) b[j] = Bs[kk * 128 + tx * 8 + j];
#pragma unroll
                for (int i = 0; i < 8; i++)
#pragma unroll
                    for (int j = 0; j < 8; j++) acc[i][j] += a[i] * b[j];
            }
            __syncthreads();
        }
#pragma unroll
        for (int i = 0; i < 8; i++) {
            int row = m0 + ty * 8 + i;
#pragma unroll
            for (int j = 0; j < 8; j++) {
                int col = n0 + tx * 8 + j;
                out[(size_t)row * VOCAB + col] = acc[i][j] + bias[col];
            }
        }
    }
#endif
}

// ---------------- tiled transpose: g_ut [D,L] -> g_u [L,D] -------------------
__global__ __launch_bounds__(256) void transpose_ut_kernel()
{
    __shared__ float tile[32][33];
    int c0 = blockIdx.x * 32;   // L dim
    int r0 = blockIdx.y * 32;   // D dim
    int x = threadIdx.x;
    int y = threadIdx.y;
#pragma unroll
    for (int i = y; i < 32; i += 8)
        tile[i][x] = g_ut[(size_t)(r0 + i) * LSEQ + c0 + x];
    __syncthreads();
#pragma unroll
    for (int i = y; i < 32; i += 8)
        g_u[(size_t)(c0 + i) * DMODEL + r0 + x] = tile[x][i];
}

// ---------------- gated B/C projections -------------------------------------
__global__ __launch_bounds__(256) void gated_bc_kernel(
    const float* __restrict__ G,
    const float* __restrict__ W1,
    const float* __restrict__ W2,
    int outSel)
{
    constexpr int RB = 32, BK = 32;
    __shared__ float Xs[RB][BK + 1];
    __shared__ float Gs[RB][BK + 1];
    __shared__ float W1s[NSTATE][BK + 1];
    __shared__ float W2s[NSTATE][BK + 1];

    const float* X = g_xin;
    float* outT = outSel ? g_Cseq : g_Bseq;

    const int r0 = blockIdx.x * RB;
    const int tid = threadIdx.x;
    const int n = tid & 31;
    const int rg = tid >> 5;

    float acc1[4] = {0.f, 0.f, 0.f, 0.f};
    float acc2[4] = {0.f, 0.f, 0.f, 0.f};

    const int plr = tid >> 3;
    const int plc = (tid & 7) * 4;

    for (int k0 = 0; k0 < DMODEL; k0 += BK) {
        float4 xv = *(const float4*)(X + (size_t)(r0 + plr) * DMODEL + k0 + plc);
        Xs[plr][plc + 0] = xv.x; Xs[plr][plc + 1] = xv.y;
        Xs[plr][plc + 2] = xv.z; Xs[plr][plc + 3] = xv.w;
        float4 gv = *(const float4*)(G + (size_t)(r0 + plr) * DMODEL + k0 + plc);
        Gs[plr][plc + 0] = gv.x; Gs[plr][plc + 1] = gv.y;
        Gs[plr][plc + 2] = gv.z; Gs[plr][plc + 3] = gv.w;
        float4 w1 = *(const float4*)(W1 + (size_t)plr * DMODEL + k0 + plc);
        W1s[plr][plc + 0] = w1.x; W1s[plr][plc + 1] = w1.y;
        W1s[plr][plc + 2] = w1.z; W1s[plr][plc + 3] = w1.w;
        float4 w2 = *(const float4*)(W2 + (size_t)plr * DMODEL + k0 + plc);
        W2s[plr][plc + 0] = w2.x; W2s[plr][plc + 1] = w2.y;
        W2s[plr][plc + 2] = w2.z; W2s[plr][plc + 3] = w2.w;
        __syncthreads();
#pragma unroll
        for (int kk = 0; kk < BK; kk++) {
            float w1v = W1s[n][kk];
            float w2v = W2s[n][kk];
#pragma unroll
            for (int i = 0; i < 4; i++) {
                acc1[i] += Xs[rg + 8 * i][kk] * w1v;
                acc2[i] += Gs[rg + 8 * i][kk] * w2v;
            }
        }
        __syncthreads();
    }
#pragma unroll
    for (int i = 0; i < 4; i++) {
        int row = r0 + rg + 8 * i;
        outT[(size_t)n * LSEQ + row] = acc1[i] * (1.0f + tanhf(acc2[i]));
    }
}

// ---------------- selective scan (exact reference Blelloch tree) -------------
__global__ __launch_bounds__(256) void scan_kernel(
    const float* __restrict__ logA)
{
    __shared__ float sa[LSEQ];
    __shared__ float sb[LSEQ];
    __shared__ float sy[LSEQ];
    __shared__ float sd[LSEQ];

    const int d = blockIdx.x;
    const int t = threadIdx.x;

    for (int l = t; l < LSEQ; l += 256) {
        sd[l] = g_delta_t[(size_t)d * LSEQ + l];
        sy[l] = 0.f;
    }
    __syncthreads();

    for (int n = 0; n < NSTATE; n++) {
        float An = -expf(logA[d * NSTATE + n]);
        float invA = 1.0f / An;
        const float* Bn = g_Bseq + (size_t)n * LSEQ;
        const float* Cn = g_Cseq + (size_t)n * LSEQ;

        for (int l = t; l < LSEQ; l += 256) {
            float ab = expf(sd[l] * An);
            sa[l] = ab;
            sb[l] = (ab - 1.f) * invA * Bn[l];
        }
        __syncthreads();

        for (int step = 1; step < LSEQ; step <<= 1) {
            int pairs = LSEQ / (2 * step);
            for (int i = t; i < pairs; i += 256) {
                int li = step - 1 + i * 2 * step;
                int ri = li + step;
                float ar = sa[ri] * sa[li];
                sb[ri] = ar * sb[li] + sb[ri];
                sa[ri] = ar;
            }
            __syncthreads();
        }
        if (t == 0) { sa[LSEQ - 1] = 1.f; sb[LSEQ - 1] = 0.f; }
        __syncthreads();

        for (int step = LSEQ >> 1; step >= 1; step >>= 1) {
            int pairs = LSEQ / (2 * step);
            for (int i = t; i < pairs; i += 256) {
                int li = step - 1 + i * 2 * step;
                int ri = li + step;
                float al = sa[li], bl = sb[li];
                float ar = sa[ri], br = sb[ri];
                float nb = ar * bl + br;
                sa[li] = ar;       sa[ri] = ar * al;
                sb[li] = nb;       sb[ri] = nb;
            }
            __syncthreads();
        }

        for (int l = t; l < LSEQ; l += 256) sy[l] += sb[l] * Cn[l];
        __syncthreads();
    }

    for (int l = t; l < LSEQ; l += 256) {
        g_ut[(size_t)d * LSEQ + l] =
            sy[l] * g_z_t[(size_t)d * LSEQ + l] + g_xin_t[(size_t)d * LSEQ + l];
    }
}

// ---------------- layernorm: g_u -> g_ln_hi/lo (bf16 split) ------------------
__global__ __launch_bounds__(256) void layernorm_kernel(
    const float* __restrict__ g, const float* __restrict__ bta)
{
    const int l = blockIdx.x;
    const int t = threadIdx.x;
    float4 v = ((const float4*)(g_u + (size_t)l * DMODEL))[t];
    float s  = v.x + v.y + v.z + v.w;
    float ss = v.x * v.x + v.y * v.y + v.z * v.z + v.w * v.w;
#pragma unroll
    for (int off = 16; off > 0; off >>= 1) {
        s  += __shfl_xor_sync(0xffffffffu, s,  off);
        ss += __shfl_xor_sync(0xffffffffu, ss, off);
    }
    __shared__ float ws[8], wss[8];
    if ((t & 31) == 0) { ws[t >> 5] = s; wss[t >> 5] = ss; }
    __syncthreads();
    float tot = 0.f, tot2 = 0.f;
#pragma unroll
    for (int w = 0; w < 8; w++) { tot += ws[w]; tot2 += wss[w]; }
    float mu  = tot * (1.0f / DMODEL);
    float var = tot2 * (1.0f / DMODEL) - mu * mu;
    float inv = rsqrtf(var + 1e-5f);

    float4 gg = ((const float4*)g)[t];
    float4 bb = ((const float4*)bta)[t];
    float rr[4];
    rr[0] = (v.x - mu) * inv * gg.x + bb.x;
    rr[1] = (v.y - mu) * inv * gg.y + bb.y;
    rr[2] = (v.z - mu) * inv * gg.z + bb.z;
    rr[3] = (v.w - mu) * inv * gg.w + bb.w;
    __nv_bfloat16 h4[4], l4[4];
#pragma unroll
    for (int j = 0; j < 4; j++) {
        __nv_bfloat16 h = __float2bfloat16(rr[j]);
        h4[j] = h;
        l4[j] = __float2bfloat16(rr[j] - __bfloat162float(h));
    }
    *(uint2*)(g_ln_hi + (size_t)l * DMODEL + t * 4) = *(uint2*)h4;
    *(uint2*)(g_ln_lo + (size_t)l * DMODEL + t * 4) = *(uint2*)l4;
}

// ---------------- launch -----------------------------------------------------
extern "C" void kernel_launch(void* const* d_in, const int* in_sizes, int n_in,
                              void* d_out, int out_size)
{
    const float* x          = (const float*)d_in[0];
    const float* b_inject   = (const float*)d_in[1];
    const float* c_inject   = (const float*)d_in[2];
    const float* W_in       = (const float*)d_in[3];
    const float* b_in       = (const float*)d_in[4];
    const float* log_A      = (const float*)d_in[5];
    const float* W_B        = (const float*)d_in[6];
    const float* W_C        = (const float*)d_in[7];
    const float* W_delta    = (const float*)d_in[8];
    const float* b_delta    = (const float*)d_in[9];
    const float* delta_bias = (const float*)d_in[10];
    const float* W_bi       = (const float*)d_in[11];
    const float* W_ci       = (const float*)d_in[12];
    const float* ln_g       = (const float*)d_in[13];
    const float* ln_b       = (const float*)d_in[14];
    const float* W_out      = (const float*)d_in[15];
    const float* b_out      = (const float*)d_in[16];
    const float* W_vocab    = (const float*)d_in[17];
    const float* b_vocab    = (const float*)d_in[18];
    float* out = (float*)d_out;

    // capture-safe, deterministic, unconditional
    cudaFuncSetAttribute(gemm_small_tc<EPI_WIN>,
                         cudaFuncAttributeMaxDynamicSharedMemorySize, VG_SMEM);
    cudaFuncSetAttribute(gemm_small_tc<EPI_DELTA>,
                         cudaFuncAttributeMaxDynamicSharedMemorySize, VG_SMEM);
    cudaFuncSetAttribute(gemm_small_tc<EPI_WOUT>,
                         cudaFuncAttributeMaxDynamicSharedMemorySize, VG_SMEM);
    cudaFuncSetAttribute(vocab_gemm_tc,
                         cudaFuncAttributeMaxDynamicSharedMemorySize, VG_SMEM);

    // 0) split x, W_in, W_delta -> bf16 hi/lo (MLP=4 streaming)
    split3_kernel<<<(N4_S3 + 1023) / 1024, 256>>>(x, W_in, W_delta);

    // 1) xz = x @ W_in^T + b_in; fused: xin (rm/t/hi/lo), z_t(sigmoid)
    gemm_small_tc<EPI_WIN><<<dim3(LSEQ / TCG_BM, 2 * DMODEL / TCG_BN), 256, VG_SMEM>>>(
        b_in, nullptr);

    // 2) gated B sequence (N x L)
    gated_bc_kernel<<<LSEQ / 32, 256>>>(b_inject, W_B, W_bi, 0);

    // 3) split W_vocab  [launch idx 3 -> ncu capture slot: measures split cost]
    split1_kernel<<<(VOCAB * DMODEL / 4 + 1023) / 1024, 256>>>(W_vocab, SEL_WV, VOCAB * DMODEL / 4);

    // 4) delta = softplus(...) -> delta_t
    gemm_small_tc<EPI_DELTA><<<dim3(LSEQ / TCG_BM, DMODEL / TCG_BN), 256, VG_SMEM>>>(
        b_delta, delta_bias);

    // 5) gated C sequence (N x L)
    gated_bc_kernel<<<LSEQ / 32, 256>>>(c_inject, W_C, W_ci, 1);

    // 6) exact-reference Blelloch scan -> ut
    scan_kernel<<<DMODEL, 256>>>(log_A);

    // 7) ut -> u
    transpose_ut_kernel<<<dim3(LSEQ / 32, DMODEL / 32), dim3(32, 8)>>>();

    // 8) layernorm -> ln hi/lo
    layernorm_kernel<<<LSEQ, 256>>>(ln_g, ln_b);

    // 9) split W_out
    split1_kernel<<<(DMODEL * DMODEL / 4 + 1023) / 1024, 256>>>(W_out, SEL_WO, DMODEL * DMODEL / 4);

    // 10) mid = ln @ W_out^T + b_out -> mid hi/lo
    gemm_small_tc<EPI_WOUT><<<dim3(LSEQ / TCG_BM, DMODEL / TCG_BN), 256, VG_SMEM>>>(
        b_out, nullptr);

    // 11) logits = mid @ W_vocab^T + b_vocab
    vocab_gemm_tc<<<dim3(LSEQ / TCG_BM, VOCAB / TCG_BN), 256, VG_SMEM>>>(b_vocab, out);
}